// round 3
// baseline (speedup 1.0000x reference)
#include <cuda_runtime.h>
#include <cstdint>

#define N_QUERIES 262144
#define N_SLOTS   1024
#define KEY_DIM   64
#define VAL_DIM   64
#define TOPK      4
#define LR        0.001f
#define MOMENTUM  0.9f
#define WD        0.0001f

#define RET_ELEMS  (N_QUERIES * TOPK * VAL_DIM)   // 67108864
#define SLOT_ELEMS (N_SLOTS * VAL_DIM)            // 65536

typedef unsigned long long u64;

// ---------------- scratch (device globals: no allocation allowed) ----------
__device__ int   g_idx[N_QUERIES * TOPK];                     // 4 MB
__device__ __align__(16) float g_sg[SLOT_ELEMS];              // slot grad sums
__device__ float g_cnt[N_SLOTS];                              // slot counts
// pair-interleaved keys: [tile(8)][k(64)][pair(64)] as u64 (lo=slot 2p, hi=2p+1)
__device__ __align__(16) u64 g_kp[8 * 64 * 64];               // 256 KB

// ---------------- f32x2 packed fma (per-lane independent fp32 FMA) ---------
__device__ __forceinline__ u64 fma2(u64 a, u64 b, u64 c) {
    u64 d;
    asm("fma.rn.f32x2 %0, %1, %2, %3;" : "=l"(d) : "l"(a), "l"(b), "l"(c));
    return d;
}

__device__ __forceinline__ void insert4(float (&tv)[4], int (&ti)[4],
                                        float sv, int jg) {
    // strict > everywhere: ties keep earlier index (stable top_k)
    if (sv > tv[3]) {
        if (sv > tv[0]) {
            tv[3]=tv[2]; ti[3]=ti[2]; tv[2]=tv[1]; ti[2]=ti[1];
            tv[1]=tv[0]; ti[1]=ti[0]; tv[0]=sv;    ti[0]=jg;
        } else if (sv > tv[1]) {
            tv[3]=tv[2]; ti[3]=ti[2]; tv[2]=tv[1]; ti[2]=ti[1];
            tv[1]=sv;    ti[1]=jg;
        } else if (sv > tv[2]) {
            tv[3]=tv[2]; ti[3]=ti[2]; tv[2]=sv;    ti[2]=jg;
        } else {
            tv[3]=sv;    ti[3]=jg;
        }
    }
}

// ---------------- kernel 0: zero accumulators + pack keys -------------------
__global__ void prep_kernel(const float* __restrict__ keys) {
    int i = blockIdx.x * blockDim.x + threadIdx.x;   // grid covers 65536
    if (i < SLOT_ELEMS) g_sg[i] = 0.0f;
    if (i < N_SLOTS)    g_cnt[i] = 0.0f;
    if (i < 8 * 64 * 64) {
        int tile = i >> 12;
        int k    = (i >> 6) & 63;
        int p    = i & 63;
        int s0   = tile * 128 + 2 * p;
        unsigned lo = __float_as_uint(keys[s0 * KEY_DIM + k]);
        unsigned hi = __float_as_uint(keys[(s0 + 1) * KEY_DIM + k]);
        g_kp[i] = ((u64)hi << 32) | lo;
    }
}

// ---------------- kernel 1: sim + exact top-4 + gather retrieved ------------
// 2 queries per thread (512 per CTA). sim[q][slot] is a SINGLE sequential fp32
// FMA chain over k=0..63 (matches single-accumulator reference order), two
// slots per f32x2 lane-pair. Per k-iter per warp: 6 LDS + 16 FFMA2 -> FMA-bound.
// SMEM: 32 KB key tile + 128 KB queries transposed [k][512] = 160 KB, 1 CTA/SM.
__global__ void __launch_bounds__(256, 1)
simtopk_kernel(const float* __restrict__ queries,
               const float* __restrict__ vals,
               float* __restrict__ retrieved) {
    extern __shared__ char smem[];
    u64*   ksh = (u64*)smem;                       // 32 KB: [k(64)][pair(64)]
    float* qsh = (float*)(smem + 32768);           // 128 KB: [k(64)][t(512)]

    const int tid   = threadIdx.x;
    const int qbase = blockIdx.x * 512;

    // stage both query rows into SMEM transposed: qsh[k*512 + (s*256+tid)]
#pragma unroll
    for (int s = 0; s < 2; s++) {
        const float4* qrow =
            (const float4*)(queries + (size_t)(qbase + s * 256 + tid) * KEY_DIM);
#pragma unroll
        for (int i = 0; i < 16; i++) {
            float4 v = qrow[i];
            qsh[(4 * i + 0) * 512 + s * 256 + tid] = v.x;
            qsh[(4 * i + 1) * 512 + s * 256 + tid] = v.y;
            qsh[(4 * i + 2) * 512 + s * 256 + tid] = v.z;
            qsh[(4 * i + 3) * 512 + s * 256 + tid] = v.w;
        }
    }

    float tv[2][4];
    int   ti[2][4];
#pragma unroll
    for (int s = 0; s < 2; s++)
#pragma unroll
        for (int r = 0; r < 4; r++) { tv[s][r] = -1e30f; ti[s][r] = 0; }

    for (int tile = 0; tile < 8; tile++) {
        __syncthreads();
        {   // cooperative load of packed key tile (32 KB contiguous)
            const float4* kg  = (const float4*)(g_kp + tile * 4096);
            float4*       ks4 = (float4*)ksh;
            for (int t = tid; t < 2048; t += 256) ks4[t] = kg[t];
        }
        __syncthreads();

        const ulonglong2* k2 = (const ulonglong2*)ksh;
        for (int pg = 0; pg < 8; pg++) {      // 8 pairs (16 slots) per group
            u64 a0[8], a1[8];
#pragma unroll
            for (int j = 0; j < 8; j++) { a0[j] = 0ull; a1[j] = 0ull; }

#pragma unroll 8
            for (int k = 0; k < 64; k++) {
                float qa = qsh[k * 512 + tid];
                float qb = qsh[k * 512 + 256 + tid];
                u64 da, db;
                asm("mov.b64 %0, {%1, %1};" : "=l"(da) : "f"(qa));
                asm("mov.b64 %0, {%1, %1};" : "=l"(db) : "f"(qb));
                int base = k * 32 + pg * 4;   // ulonglong2 index
                ulonglong2 c0 = k2[base + 0];
                ulonglong2 c1 = k2[base + 1];
                ulonglong2 c2 = k2[base + 2];
                ulonglong2 c3 = k2[base + 3];
                a0[0] = fma2(da, c0.x, a0[0]);  a1[0] = fma2(db, c0.x, a1[0]);
                a0[1] = fma2(da, c0.y, a0[1]);  a1[1] = fma2(db, c0.y, a1[1]);
                a0[2] = fma2(da, c1.x, a0[2]);  a1[2] = fma2(db, c1.x, a1[2]);
                a0[3] = fma2(da, c1.y, a0[3]);  a1[3] = fma2(db, c1.y, a1[3]);
                a0[4] = fma2(da, c2.x, a0[4]);  a1[4] = fma2(db, c2.x, a1[4]);
                a0[5] = fma2(da, c2.y, a0[5]);  a1[5] = fma2(db, c2.y, a1[5]);
                a0[6] = fma2(da, c3.x, a0[6]);  a1[6] = fma2(db, c3.x, a1[6]);
                a0[7] = fma2(da, c3.y, a0[7]);  a1[7] = fma2(db, c3.y, a1[7]);
            }

            int sbase = tile * 128 + pg * 16;
#pragma unroll
            for (int pp = 0; pp < 8; pp++) {
                float l0 = __uint_as_float((unsigned)a0[pp]);
                float h0 = __uint_as_float((unsigned)(a0[pp] >> 32));
                float l1 = __uint_as_float((unsigned)a1[pp]);
                float h1 = __uint_as_float((unsigned)(a1[pp] >> 32));
                insert4(tv[0], ti[0], l0, sbase + 2 * pp);
                insert4(tv[0], ti[0], h0, sbase + 2 * pp + 1);
                insert4(tv[1], ti[1], l1, sbase + 2 * pp);
                insert4(tv[1], ti[1], h1, sbase + 2 * pp + 1);
            }
        }
    }

    // epilogue: indices + gather retrieved rows (vals is L2-resident, 256 KB)
#pragma unroll
    for (int s = 0; s < 2; s++) {
        int q = qbase + s * 256 + tid;
        float4* out4 = (float4*)(retrieved + (size_t)q * (TOPK * VAL_DIM));
#pragma unroll
        for (int r = 0; r < TOPK; r++) {
            int id = ti[s][r];
            g_idx[q * TOPK + r] = id;
            const float4* vr = (const float4*)(vals + (size_t)id * VAL_DIM);
#pragma unroll
            for (int t = 0; t < 16; t++) out4[r * 16 + t] = vr[t];
        }
    }
}

// ---------------- kernel 2: scatter grads via direct global v4 reductions ---
// 16.7M float4 words, grid-stride, perfectly coalesced. Each word REDs into
// its slot row; one count RED per entry from the c4==0 lane.
#define W_TOTAL (RET_ELEMS / 4)          // 16777216
#define SCAT_THREADS (2048 * 256)        // 32 iters each, exact
__global__ void __launch_bounds__(256)
scatter_kernel(const float4* __restrict__ grads4) {
    int t = blockIdx.x * 256 + threadIdx.x;
#pragma unroll 4
    for (int it = 0; it < W_TOTAL / SCAT_THREADS; it++) {
        int w    = t + it * SCAT_THREADS;
        int e    = w >> 4;
        int c4   = w & 15;
        int slot = __ldg(&g_idx[e]);
        float4 g = __ldg(&grads4[w]);
        float* dst = &g_sg[slot * VAL_DIM + c4 * 4];
        asm volatile("red.global.add.v4.f32 [%0], {%1, %2, %3, %4};"
                     :: "l"(dst), "f"(g.x), "f"(g.y), "f"(g.z), "f"(g.w)
                     : "memory");
        if (c4 == 0) atomicAdd(&g_cnt[slot], 1.0f);
    }
}

// ---------------- kernel 3: finalize vals_new / mom_new ---------------------
__global__ void finalize_kernel(const float* __restrict__ vals,
                                const float* __restrict__ mom,
                                float* __restrict__ out) {
    int i = blockIdx.x * blockDim.x + threadIdx.x;   // 0..65535
    if (i >= SLOT_ELEMS) return;
    int   slot = i >> 6;
    float c    = g_cnt[slot];
    float sgv  = g_sg[i];
    bool  nz   = c > 0.0f;
    float avg  = nz ? (sgv / c) : sgv;
    float mn   = MOMENTUM * mom[i] + avg;
    float delta = -LR * (mn + WD * vals[i]);
    float vn   = vals[i] + (nz ? delta : 0.0f);
    out[RET_ELEMS + i]              = vn;            // vals_new
    out[RET_ELEMS + SLOT_ELEMS + i] = mn;            // mom_new
}

// ---------------- launch ----------------------------------------------------
extern "C" void kernel_launch(void* const* d_in, const int* in_sizes, int n_in,
                              void* d_out, int out_size) {
    const float* queries = (const float*)d_in[0];
    const float* keys    = (const float*)d_in[1];
    const float* vals    = (const float*)d_in[2];
    const float* mom     = (const float*)d_in[3];
    const float* grads   = (const float*)d_in[4];
    float* out = (float*)d_out;

    static bool attr_set = false;
    if (!attr_set) {
        cudaFuncSetAttribute(simtopk_kernel,
                             cudaFuncAttributeMaxDynamicSharedMemorySize,
                             163840);   // 32 KB keys + 128 KB queries
        attr_set = true;
    }

    prep_kernel<<<256, 256>>>(keys);
    simtopk_kernel<<<N_QUERIES / 512, 256, 163840>>>(queries, vals, out);
    scatter_kernel<<<2048, 256>>>((const float4*)grads);
    finalize_kernel<<<256, 256>>>(vals, mom, out);
}